// round 9
// baseline (speedup 1.0000x reference)
#include <cuda_runtime.h>
#include <cstdint>
#include <cstddef>

#define NRAYS   65536
#define NPTS    32
#define FEAT    128
#define DIM     512
#define NLAYERS 6
#define KIN     4096          // NPTS * FEAT
#define LN_EPS  1e-5f

// ---------------- scratch (device globals: allocation-free) ----------------
__device__ float g_X[268435456];        // [NRAYS, KIN] fp32, 1 GB
__device__ float g_Ha[33554432];        // [NRAYS, DIM]
__device__ float g_Hb[33554432];        // [NRAYS, DIM]
__device__ float g_A [33554432];        // [NRAYS, DIM] (post relu+LN)
__device__ float g_len[NRAYS];
__device__ int   g_mask_mode;           // 0=word(!=0): int32/float32, 2=uint8, 3=bf16
__device__ unsigned char g_mask[NRAYS]; // canonical 0/1 mask

// ---------------- kernel 0a: sniff the mask dtype ----------------
// Scans the first 16384 words (64 KB) — valid for every candidate width
// (uint8 buffer = 64 KB exactly, bf16 = 128 KB, int32/float32 = 256 KB).
__global__ void mask_detect(const unsigned* __restrict__ w)
{
    __shared__ int s_u8, s_bf16;
    if (threadIdx.x == 0) { s_u8 = 0; s_bf16 = 0; }
    __syncthreads();
    int u8 = 0, bf = 0;
    for (int i = threadIdx.x; i < 16384; i += blockDim.x) {
        unsigned v = w[i];
        if (v == 0x3F803F80u || v == 0x00003F80u) bf = 1;                 // bf16 1.0 pairs
        else if (v > 1u && (v & ~0x01010101u) == 0u) u8 = 1;              // packed bool bytes
    }
    if (u8) atomicOr(&s_u8, 1);
    if (bf) atomicOr(&s_bf16, 1);
    __syncthreads();
    if (threadIdx.x == 0) {
        int mode = 0;                  // default: 32-bit word != 0 (int32 OR float32)
        if (s_bf16) mode = 3;
        if (s_u8)   mode = 2;
        g_mask_mode = mode;
    }
}

// ---------------- kernel 0b: canonicalize mask -> g_mask ----------------
__global__ void mask_decode(const void* __restrict__ mp)
{
    int r = blockIdx.x * blockDim.x + threadIdx.x;
    if (r >= NRAYS) return;
    int mode = g_mask_mode;
    unsigned char m;
    if (mode == 2)      m = (((const unsigned char*)mp)[r]  != 0);
    else if (mode == 3) m = (((const unsigned short*)mp)[r] != 0);
    else                m = (((const unsigned*)mp)[r]       != 0);
    g_mask[r] = m;
}

// ---------------- kernel 1: trilinear interp -> X ----------------
__global__ __launch_bounds__(128)
void interp_kernel(const float* __restrict__ orig, const float* __restrict__ vec,
                   const float* __restrict__ t1, const float* __restrict__ t2,
                   const float* __restrict__ nmin, const float* __restrict__ nmax,
                   const float* __restrict__ bbox, const int* __restrict__ idxs)
{
    const int r = blockIdx.x;
    const int tid = threadIdx.x;            // 128 threads
    __shared__ float sf[8][FEAT];           // gathered features, 4 KB
    __shared__ float so[3], se[3];

    const int idx = (g_mask[r] != 0) ? idxs[r] : 0;

    // gather bbox_features row (1024 floats) coalesced
    const float4* fsrc = (const float4*)(bbox + (size_t)idx * 1024);
    float4* fdst = (float4*)&sf[0][0];
    fdst[tid]       = fsrc[tid];
    fdst[tid + 128] = fsrc[tid + 128];

    if (tid < 3) {
        float o_  = orig[r * 3 + tid];
        float v   = vec [r * 3 + tid];
        float a   = t1[r], b = t2[r];
        float io  = o_ + v * a;
        float iv  = v * (b - a);
        float ie  = io + iv;
        float mn  = nmin[idx * 3 + tid];
        float ext = nmax[idx * 3 + tid] - mn;
        so[tid] = fminf(fmaxf((io - mn) / ext, 0.f), 1.f);
        se[tid] = fminf(fmaxf((ie - mn) / ext, 0.f), 1.f);
    }
    if (tid == 0) {
        float s = t2[r] - t1[r];
        float vx = vec[r*3+0] * s, vy = vec[r*3+1] * s, vz = vec[r*3+2] * s;
        g_len[r] = sqrtf(vx*vx + vy*vy + vz*vz);
    }
    __syncthreads();

    const float ox = so[0], oy = so[1], oz = so[2];
    const float dx = se[0] - ox, dy = se[1] - oy, dz = se[2] - oz;
    float* Xrow = g_X + (size_t)r * KIN;

    const float f0 = sf[0][tid], f1 = sf[1][tid], f2 = sf[2][tid], f3 = sf[3][tid];
    const float f4 = sf[4][tid], f5 = sf[5][tid], f6 = sf[6][tid], f7 = sf[7][tid];

    #pragma unroll
    for (int p = 0; p < NPTS; p++) {
        float t = (float)p * (1.0f / (NPTS - 1));
        float x = ox + dx * t, y = oy + dy * t, z = oz + dz * t;
        float ix = 1.f - x, iy = 1.f - y, iz = 1.f - z;
        // order: f000,f100,f010,f001,f101,f011,f110,f111
        float v = (ix*iy*iz) * f0 + (x*iy*iz) * f1 + (ix*y*iz) * f2 + (ix*iy*z) * f3
                + (x*iy*z)  * f4 + (ix*y*z)  * f5 + (x*y*iz)  * f6 + (x*y*z)   * f7;
        Xrow[p * FEAT + tid] = v;
    }
}

// ---------------- kernel 2: fp32 TN GEMM via fma.rn.f32x2 ----------------
// C[M,N] = A[M,K] @ W[N,K]^T + bias[N]
// Tile 256(M) x 128(N), BK=8, 256 threads, per-thread 16x8 outputs as 8x8 f32x2.
__global__ __launch_bounds__(256, 1)
void gemm_tn(const float* __restrict__ A, const float* __restrict__ W,
             const float* __restrict__ bias, float* __restrict__ C,
             int M, int N, int K)
{
    __shared__ __align__(16) float As[8][256];
    __shared__ __align__(16) float Ws[8][132];   // padded to kill store bank conflicts

    const int tid = threadIdx.x;
    const int bm  = blockIdx.x * 256;
    const int bn  = blockIdx.y * 128;
    const int tx  = tid & 15;          // n group
    const int ty  = tid >> 4;          // m group
    const int m0  = ty * 16;
    const int n0  = tx * 8;

    const float* Ap = A + (size_t)(bm + tid) * K;           // one A row / thread
    const int wrow = tid >> 1;
    const int wkq  = (tid & 1) * 4;
    const float* Wp = W + (size_t)(bn + wrow) * K + wkq;

    unsigned long long acc[8][8];
    #pragma unroll
    for (int i = 0; i < 8; i++)
        #pragma unroll
        for (int j = 0; j < 8; j++) acc[i][j] = 0ull;

    // prefetch first tile
    float4 a0 = *(const float4*)(Ap + 0);
    float4 a1 = *(const float4*)(Ap + 4);
    float4 w0 = *(const float4*)(Wp + 0);

    for (int k0 = 0; k0 < K; k0 += 8) {
        // commit prefetched tile to smem
        As[0][tid] = a0.x; As[1][tid] = a0.y; As[2][tid] = a0.z; As[3][tid] = a0.w;
        As[4][tid] = a1.x; As[5][tid] = a1.y; As[6][tid] = a1.z; As[7][tid] = a1.w;
        Ws[wkq+0][wrow] = w0.x; Ws[wkq+1][wrow] = w0.y;
        Ws[wkq+2][wrow] = w0.z; Ws[wkq+3][wrow] = w0.w;
        __syncthreads();

        // issue next tile's global loads early (latency hidden by compute)
        if (k0 + 8 < K) {
            a0 = *(const float4*)(Ap + k0 + 8);
            a1 = *(const float4*)(Ap + k0 + 12);
            w0 = *(const float4*)(Wp + k0 + 8);
        }

        #pragma unroll
        for (int kk = 0; kk < 8; kk++) {
            unsigned long long a2[8];
            const unsigned long long* ap = (const unsigned long long*)&As[kk][m0];
            #pragma unroll
            for (int i = 0; i < 8; i++) a2[i] = ap[i];

            float bvv[8];
            *(float4*)&bvv[0] = *(const float4*)&Ws[kk][n0];
            *(float4*)&bvv[4] = *(const float4*)&Ws[kk][n0 + 4];

            #pragma unroll
            for (int j = 0; j < 8; j++) {
                unsigned long long b2;
                asm("mov.b64 %0, {%1, %1};" : "=l"(b2) : "r"(__float_as_uint(bvv[j])));
                #pragma unroll
                for (int i = 0; i < 8; i++)
                    asm("fma.rn.f32x2 %0, %1, %2, %0;"
                        : "+l"(acc[i][j]) : "l"(a2[i]), "l"(b2));
            }
        }
        __syncthreads();
    }

    // epilogue: + bias, store
    float bb[8];
    *(float4*)&bb[0] = *(const float4*)&bias[bn + n0];
    *(float4*)&bb[4] = *(const float4*)&bias[bn + n0 + 4];

    #pragma unroll
    for (int i = 0; i < 8; i++) {
        float r0[8], r1[8];
        #pragma unroll
        for (int j = 0; j < 8; j++) {
            unsigned long long v = acc[i][j];
            r0[j] = __uint_as_float((unsigned)(v       )) + bb[j];  // even row
            r1[j] = __uint_as_float((unsigned)(v >> 32 )) + bb[j];  // odd row
        }
        size_t base0 = (size_t)(bm + m0 + 2*i) * N + bn + n0;
        *(float4*)&C[base0]       = make_float4(r0[0], r0[1], r0[2], r0[3]);
        *(float4*)&C[base0 + 4]   = make_float4(r0[4], r0[5], r0[6], r0[7]);
        size_t base1 = base0 + N;
        *(float4*)&C[base1]       = make_float4(r1[0], r1[1], r1[2], r1[3]);
        *(float4*)&C[base1 + 4]   = make_float4(r1[4], r1[5], r1[6], r1[7]);
    }
}

// ---------------- kernel 3: relu + layernorm (warp per row) ----------------
__global__ __launch_bounds__(256)
void relu_ln_kernel(const float* __restrict__ H, const float* __restrict__ g,
                    const float* __restrict__ beta, float* __restrict__ Aout)
{
    const int warp = (blockIdx.x * blockDim.x + threadIdx.x) >> 5;
    const int lane = threadIdx.x & 31;
    if (warp >= NRAYS) return;
    const float* row = H + (size_t)warp * DIM;

    float x[16];
    float s = 0.f;
    #pragma unroll
    for (int j = 0; j < 16; j++) {
        x[j] = fmaxf(row[lane + 32 * j], 0.f);
        s += x[j];
    }
    #pragma unroll
    for (int o = 16; o; o >>= 1) s += __shfl_xor_sync(0xffffffffu, s, o);
    const float mu = s * (1.0f / DIM);

    float vs = 0.f;
    #pragma unroll
    for (int j = 0; j < 16; j++) { float d = x[j] - mu; vs += d * d; }
    #pragma unroll
    for (int o = 16; o; o >>= 1) vs += __shfl_xor_sync(0xffffffffu, vs, o);
    const float rs = rsqrtf(vs * (1.0f / DIM) + LN_EPS);

    float* orow = Aout + (size_t)warp * DIM;
    #pragma unroll
    for (int j = 0; j < 16; j++) {
        int c = lane + 32 * j;
        orow[c] = (x[j] - mu) * rs * g[c] + beta[c];
    }
}

// ---------------- kernel 4: heads + epilogue (warp per row) ----------------
__global__ __launch_bounds__(256)
void head_kernel(const float* __restrict__ H,
                 const float* __restrict__ Wcls, const float* __restrict__ bcls,
                 const float* __restrict__ Wdist, const float* __restrict__ bdist,
                 const float* __restrict__ t1, const float* __restrict__ dist_in,
                 float* __restrict__ out)
{
    const int warp = (blockIdx.x * blockDim.x + threadIdx.x) >> 5;
    const int lane = threadIdx.x & 31;
    if (warp >= NRAYS) return;
    const float* row = H + (size_t)warp * DIM;

    float sc = 0.f, sd = 0.f;
    #pragma unroll
    for (int j = 0; j < 16; j++) {
        int c = lane + 32 * j;
        float h = fmaxf(row[c], 0.f);
        sc += h * Wcls[c];
        sd += h * Wdist[c];
    }
    #pragma unroll
    for (int o = 16; o; o >>= 1) {
        sc += __shfl_xor_sync(0xffffffffu, sc, o);
        sd += __shfl_xor_sync(0xffffffffu, sd, o);
    }

    if (lane == 0) {
        const int r = warp;
        float cls  = sc + bcls[0];
        float dist = (sd + bdist[0]) * g_len[r];
        bool  m    = (g_mask[r] != 0);
        float hit  = m ? cls : 0.f;
        float dval = (m ? dist : 0.f) + t1[r];
        float di   = dist_in[r];
        bool  up   = (hit > 0.f) && (dval < di) && m;
        out[r]         = hit;
        out[NRAYS + r] = up ? dval : di;
    }
}

// ---------------- launch ----------------
extern "C" void kernel_launch(void* const* d_in, const int* in_sizes, int n_in,
                              void* d_out, int out_size)
{
    const float* orig    = (const float*)d_in[0];
    const float* vec     = (const float*)d_in[1];
    const float* t1      = (const float*)d_in[2];
    const float* t2      = (const float*)d_in[3];
    const float* dist_in = (const float*)d_in[4];
    const float* nmin    = (const float*)d_in[5];
    const float* nmax    = (const float*)d_in[6];
    const float* bbox    = (const float*)d_in[7];
    const float* W0      = (const float*)d_in[8];
    const float* b0      = (const float*)d_in[9];
    const float* Wl      = (const float*)d_in[10];
    const float* bl      = (const float*)d_in[11];
    const float* gl      = (const float*)d_in[12];
    const float* betal   = (const float*)d_in[13];
    const float* Wcls    = (const float*)d_in[14];
    const float* bcls    = (const float*)d_in[15];
    const float* Wdist   = (const float*)d_in[16];
    const float* bdist   = (const float*)d_in[17];
    const int*   idxs    = (const int*)d_in[18];
    const void*  maskraw = (const void*)d_in[19];
    float* out = (float*)d_out;

    float *pX = nullptr, *pHa = nullptr, *pHb = nullptr, *pA = nullptr;
    cudaGetSymbolAddress((void**)&pX,  g_X);
    cudaGetSymbolAddress((void**)&pHa, g_Ha);
    cudaGetSymbolAddress((void**)&pHb, g_Hb);
    cudaGetSymbolAddress((void**)&pA,  g_A);

    // 0) sniff mask dtype, canonicalize to g_mask
    mask_detect<<<1, 1024>>>((const unsigned*)maskraw);
    mask_decode<<<NRAYS / 256, 256>>>(maskraw);

    // 1) interp -> X [NRAYS, 4096]
    interp_kernel<<<NRAYS, 128>>>(orig, vec, t1, t2, nmin, nmax, bbox, idxs);

    // 2) H = X @ W0^T + b0
    gemm_tn<<<dim3(NRAYS / 256, DIM / 128), 256>>>(pX, W0, b0, pHa, NRAYS, DIM, KIN);

    // 3) 6 x (relu -> LN -> GEMM)
    float* cur = pHa;
    float* nxt = pHb;
    for (int i = 0; i < NLAYERS; i++) {
        relu_ln_kernel<<<(NRAYS * 32) / 256, 256>>>(cur, gl + i * DIM, betal + i * DIM, pA);
        gemm_tn<<<dim3(NRAYS / 256, DIM / 128), 256>>>(pA, Wl + (size_t)i * DIM * DIM,
                                                       bl + i * DIM, nxt, NRAYS, DIM, DIM);
        float* tmp = cur; cur = nxt; nxt = tmp;
    }

    // 4) heads + select epilogue
    head_kernel<<<(NRAYS * 32) / 256, 256>>>(cur, Wcls, bcls, Wdist, bdist,
                                             t1, dist_in, out);
}

// round 10
// speedup vs baseline: 1.1584x; 1.1584x over previous
#include <cuda_runtime.h>
#include <cuda_fp16.h>
#include <cstdint>
#include <cstddef>

#define NRAYS   65536
#define NPTS    32
#define FEAT    128
#define DIM     512
#define NLAYERS 6
#define KIN     4096
#define LN_EPS  1e-5f
#define RESCUE_CAP 4096
#define RESCUE_TAU 1.0e-3f

// ---------------- scratch (device globals: allocation-free) ----------------
__device__ __half g_Xh[268435456];      // [NRAYS, KIN] hi fp16 (512MB)
__device__ __half g_Xl[268435456];      // lo fp16
__device__ float  g_Ha[33554432];       // [NRAYS, DIM] fp32
__device__ float  g_Hb[33554432];
__device__ __half g_Ah[33554432];       // post relu+LN hi
__device__ __half g_Al[33554432];       // lo
__device__ __half g_W0h[2097152], g_W0l[2097152];   // W0 split
__device__ __half g_Wlh[1572864], g_Wll[1572864];   // Wl split (6 layers)
__device__ float  g_W0T[2097152];       // W0^T [4096][512] for rescue
__device__ float  g_WlT[1572864];       // Wl^T per layer [512][512]
__device__ float  g_len[NRAYS];
__device__ int    g_mask_mode;
__device__ unsigned char g_mask[NRAYS];
__device__ int    g_rescue_cnt;
__device__ int    g_rescue_list[RESCUE_CAP];

// ---------------- mask dtype sniff + decode (unchanged, proven) ----------------
__global__ void mask_detect(const unsigned* __restrict__ w)
{
    __shared__ int s_u8, s_bf16;
    if (threadIdx.x == 0) { s_u8 = 0; s_bf16 = 0; }
    __syncthreads();
    int u8 = 0, bf = 0;
    for (int i = threadIdx.x; i < 16384; i += blockDim.x) {
        unsigned v = w[i];
        if (v == 0x3F803F80u || v == 0x00003F80u) bf = 1;
        else if (v > 1u && (v & ~0x01010101u) == 0u) u8 = 1;
    }
    if (u8) atomicOr(&s_u8, 1);
    if (bf) atomicOr(&s_bf16, 1);
    __syncthreads();
    if (threadIdx.x == 0) {
        int mode = 0;
        if (s_bf16) mode = 3;
        if (s_u8)   mode = 2;
        g_mask_mode = mode;
        g_rescue_cnt = 0;          // zero rescue counter each launch
    }
}

__global__ void mask_decode(const void* __restrict__ mp)
{
    int r = blockIdx.x * blockDim.x + threadIdx.x;
    if (r >= NRAYS) return;
    int mode = g_mask_mode;
    unsigned char m;
    if (mode == 2)      m = (((const unsigned char*)mp)[r]  != 0);
    else if (mode == 3) m = (((const unsigned short*)mp)[r] != 0);
    else                m = (((const unsigned*)mp)[r]       != 0);
    g_mask[r] = m;
}

// ---------------- weight split + transpose prep ----------------
__global__ void split_kernel(const float* __restrict__ s, __half* __restrict__ hi,
                             __half* __restrict__ lo, int n)
{
    int i = blockIdx.x * blockDim.x + threadIdx.x;
    if (i >= n) return;
    float v = s[i];
    __half h = __float2half_rn(v);
    hi[i] = h;
    lo[i] = __float2half_rn(v - __half2float(h));
}

__global__ void transpose_k(const float* __restrict__ src, float* __restrict__ dst,
                            int R, int C)   // src[R][C] -> dst[C][R]
{
    __shared__ float tile[32][33];
    int bx = blockIdx.x * 32, by = blockIdx.y * 32;
    int tx = threadIdx.x, ty = threadIdx.y;
    #pragma unroll
    for (int i = 0; i < 32; i += 8) {
        int rr = by + ty + i, cc = bx + tx;
        if (rr < R && cc < C) tile[ty + i][tx] = src[(size_t)rr * C + cc];
    }
    __syncthreads();
    #pragma unroll
    for (int i = 0; i < 32; i += 8) {
        int cc = bx + ty + i, rr = by + tx;
        if (cc < C && rr < R) dst[(size_t)cc * R + rr] = tile[tx][ty + i];
    }
}

// ---------------- kernel 1: trilinear interp -> Xh/Xl fp16 split ----------------
__global__ __launch_bounds__(128)
void interp_kernel(const float* __restrict__ orig, const float* __restrict__ vec,
                   const float* __restrict__ t1, const float* __restrict__ t2,
                   const float* __restrict__ nmin, const float* __restrict__ nmax,
                   const float* __restrict__ bbox, const int* __restrict__ idxs)
{
    const int r = blockIdx.x;
    const int tid = threadIdx.x;
    __shared__ float sf[8][FEAT];
    __shared__ float so[3], se[3];

    const int idx = (g_mask[r] != 0) ? idxs[r] : 0;

    const float4* fsrc = (const float4*)(bbox + (size_t)idx * 1024);
    float4* fdst = (float4*)&sf[0][0];
    fdst[tid]       = fsrc[tid];
    fdst[tid + 128] = fsrc[tid + 128];

    if (tid < 3) {
        float o_  = orig[r * 3 + tid];
        float v   = vec [r * 3 + tid];
        float a   = t1[r], b = t2[r];
        float io  = o_ + v * a;
        float iv  = v * (b - a);
        float ie  = io + iv;
        float mn  = nmin[idx * 3 + tid];
        float ext = nmax[idx * 3 + tid] - mn;
        so[tid] = fminf(fmaxf((io - mn) / ext, 0.f), 1.f);
        se[tid] = fminf(fmaxf((ie - mn) / ext, 0.f), 1.f);
    }
    if (tid == 0) {
        float s = t2[r] - t1[r];
        float vx = vec[r*3+0] * s, vy = vec[r*3+1] * s, vz = vec[r*3+2] * s;
        g_len[r] = sqrtf(vx*vx + vy*vy + vz*vz);
    }
    __syncthreads();

    const float ox = so[0], oy = so[1], oz = so[2];
    const float dx = se[0] - ox, dy = se[1] - oy, dz = se[2] - oz;

    const float f0 = sf[0][tid], f1 = sf[1][tid], f2 = sf[2][tid], f3 = sf[3][tid];
    const float f4 = sf[4][tid], f5 = sf[5][tid], f6 = sf[6][tid], f7 = sf[7][tid];

    size_t base = (size_t)r * KIN;
    #pragma unroll
    for (int p = 0; p < NPTS; p++) {
        float t = (float)p * (1.0f / (NPTS - 1));
        float x = ox + dx * t, y = oy + dy * t, z = oz + dz * t;
        float ix = 1.f - x, iy = 1.f - y, iz = 1.f - z;
        float v = (ix*iy*iz) * f0 + (x*iy*iz) * f1 + (ix*y*iz) * f2 + (ix*iy*z) * f3
                + (x*iy*z)  * f4 + (ix*y*z)  * f5 + (x*y*iz)  * f6 + (x*y*z)   * f7;
        __half h = __float2half_rn(v);
        size_t off = base + p * FEAT + tid;
        g_Xh[off] = h;
        g_Xl[off] = __float2half_rn(v - __half2float(h));
    }
}

// ---------------- kernel 2: fp16x3 split TN GEMM on tensor cores ----------------
// C[M,N] = (Ah+Al)[M,K] @ (Wh+Wl)[N,K]^T + bias  (drops Al*Wl, ~2^-24 rel)
// BM=128, BN=128, BK=16, 256 threads (8 warps as 2m x 4n), cp.async double buffer.
__device__ __forceinline__ void cp16(uint32_t s, const void* g)
{
    asm volatile("cp.async.cg.shared.global [%0], [%1], 16;" :: "r"(s), "l"(g));
}
#define MMA16816(d, a, b) \
    asm volatile("mma.sync.aligned.m16n8k16.row.col.f32.f16.f16.f32 " \
        "{%0,%1,%2,%3},{%4,%5,%6,%7},{%8,%9},{%0,%1,%2,%3};" \
        : "+f"(d[0]), "+f"(d[1]), "+f"(d[2]), "+f"(d[3]) \
        : "r"(a[0]), "r"(a[1]), "r"(a[2]), "r"(a[3]), "r"(b[0]), "r"(b[1]))

__global__ __launch_bounds__(256, 1)
void gemm_f16x3(const __half* __restrict__ Ah, const __half* __restrict__ Al,
                const __half* __restrict__ Wh, const __half* __restrict__ Wl,
                const float* __restrict__ bias, float* __restrict__ C,
                int M, int N, int K)
{
    // [stage][split][row 128][24 halves] ; 48 KB total static
    __shared__ __align__(16) __half sA[2][2][128][24];
    __shared__ __align__(16) __half sW[2][2][128][24];

    const int tid  = threadIdx.x;
    const int bm   = blockIdx.x * 128;
    const int bn   = blockIdx.y * 128;
    const int lane = tid & 31;
    const int wid  = tid >> 5;
    const int wm   = wid >> 2;           // 0..1
    const int wn   = wid & 3;            // 0..3
    const int g    = lane >> 2;          // 0..7
    const int c4   = lane & 3;           // 0..3

    // loader mapping: thread covers one 16B chunk per array per stage
    const int lrow  = tid >> 1;          // 0..127
    const int lcol8 = (tid & 1) * 8;     // 0 or 8 halves
    const __half* gAh = Ah + (size_t)(bm + lrow) * K + lcol8;
    const __half* gAl = Al + (size_t)(bm + lrow) * K + lcol8;
    const __half* gWh = Wh + (size_t)(bn + lrow) * K + lcol8;
    const __half* gWl = Wl + (size_t)(bn + lrow) * K + lcol8;

    const uint32_t aBase = (uint32_t)__cvta_generic_to_shared(&sA[0][0][0][0]);
    const uint32_t wBase = (uint32_t)__cvta_generic_to_shared(&sW[0][0][0][0]);
    const uint32_t rowoff = lrow * 48 + lcol8 * 2;          // bytes
    const uint32_t STG = 2 * 128 * 24 * 2;                  // 12288 bytes/stage
    const uint32_t SPL = 128 * 24 * 2;                      // 6144 bytes/split

    float acc[4][4][4];
    #pragma unroll
    for (int i = 0; i < 4; i++)
        #pragma unroll
        for (int j = 0; j < 4; j++)
            #pragma unroll
            for (int q = 0; q < 4; q++) acc[i][j][q] = 0.f;

    const int NS = K >> 4;

    // prologue: stages 0,1
    #pragma unroll
    for (int s = 0; s < 2; s++) {
        int k0 = s * 16;
        cp16(aBase + s * STG + rowoff,       gAh + k0);
        cp16(aBase + s * STG + SPL + rowoff, gAl + k0);
        cp16(wBase + s * STG + rowoff,       gWh + k0);
        cp16(wBase + s * STG + SPL + rowoff, gWl + k0);
        asm volatile("cp.async.commit_group;");
    }

    for (int s = 0; s < NS; s++) {
        if (s < NS - 1) asm volatile("cp.async.wait_group 1;");
        else            asm volatile("cp.async.wait_group 0;");
        __syncthreads();
        const int p = s & 1;

        uint32_t AH[4][4], AL[4][4], BH[4][2], BL[4][2];
        #pragma unroll
        for (int mt = 0; mt < 4; mt++) {
            int r0 = wm * 64 + mt * 16 + g;
            AH[mt][0] = *(const uint32_t*)&sA[p][0][r0    ][2 * c4];
            AH[mt][1] = *(const uint32_t*)&sA[p][0][r0 + 8][2 * c4];
            AH[mt][2] = *(const uint32_t*)&sA[p][0][r0    ][2 * c4 + 8];
            AH[mt][3] = *(const uint32_t*)&sA[p][0][r0 + 8][2 * c4 + 8];
            AL[mt][0] = *(const uint32_t*)&sA[p][1][r0    ][2 * c4];
            AL[mt][1] = *(const uint32_t*)&sA[p][1][r0 + 8][2 * c4];
            AL[mt][2] = *(const uint32_t*)&sA[p][1][r0    ][2 * c4 + 8];
            AL[mt][3] = *(const uint32_t*)&sA[p][1][r0 + 8][2 * c4 + 8];
        }
        #pragma unroll
        for (int nt = 0; nt < 4; nt++) {
            int rn = wn * 32 + nt * 8 + g;
            BH[nt][0] = *(const uint32_t*)&sW[p][0][rn][2 * c4];
            BH[nt][1] = *(const uint32_t*)&sW[p][0][rn][2 * c4 + 8];
            BL[nt][0] = *(const uint32_t*)&sW[p][1][rn][2 * c4];
            BL[nt][1] = *(const uint32_t*)&sW[p][1][rn][2 * c4 + 8];
        }
        #pragma unroll
        for (int mt = 0; mt < 4; mt++)
            #pragma unroll
            for (int nt = 0; nt < 4; nt++) {
                MMA16816(acc[mt][nt], AH[mt], BH[nt]);
                MMA16816(acc[mt][nt], AH[mt], BL[nt]);
                MMA16816(acc[mt][nt], AL[mt], BH[nt]);
            }
        __syncthreads();

        if (s + 2 < NS) {
            int k0 = (s + 2) * 16;
            cp16(aBase + p * STG + rowoff,       gAh + k0);
            cp16(aBase + p * STG + SPL + rowoff, gAl + k0);
            cp16(wBase + p * STG + rowoff,       gWh + k0);
            cp16(wBase + p * STG + SPL + rowoff, gWl + k0);
            asm volatile("cp.async.commit_group;");
        }
    }

    // epilogue
    float2 bb[4];
    #pragma unroll
    for (int nt = 0; nt < 4; nt++)
        bb[nt] = *(const float2*)&bias[bn + wn * 32 + nt * 8 + c4 * 2];

    #pragma unroll
    for (int mt = 0; mt < 4; mt++) {
        int m = bm + wm * 64 + mt * 16 + g;
        #pragma unroll
        for (int nt = 0; nt < 4; nt++) {
            int n = bn + wn * 32 + nt * 8 + c4 * 2;
            float2 v0 = make_float2(acc[mt][nt][0] + bb[nt].x, acc[mt][nt][1] + bb[nt].y);
            float2 v1 = make_float2(acc[mt][nt][2] + bb[nt].x, acc[mt][nt][3] + bb[nt].y);
            *(float2*)&C[(size_t)m * N + n]       = v0;
            *(float2*)&C[(size_t)(m + 8) * N + n] = v1;
        }
    }
}

// ---------------- kernel 3: relu + layernorm -> split fp16 ----------------
__global__ __launch_bounds__(256)
void relu_ln_kernel(const float* __restrict__ H, const float* __restrict__ g,
                    const float* __restrict__ beta)
{
    const int warp = (blockIdx.x * blockDim.x + threadIdx.x) >> 5;
    const int lane = threadIdx.x & 31;
    if (warp >= NRAYS) return;
    const float* row = H + (size_t)warp * DIM;

    float x[16];
    float s = 0.f;
    #pragma unroll
    for (int j = 0; j < 16; j++) {
        x[j] = fmaxf(row[lane + 32 * j], 0.f);
        s += x[j];
    }
    #pragma unroll
    for (int o = 16; o; o >>= 1) s += __shfl_xor_sync(0xffffffffu, s, o);
    const float mu = s * (1.0f / DIM);

    float vs = 0.f;
    #pragma unroll
    for (int j = 0; j < 16; j++) { float d = x[j] - mu; vs += d * d; }
    #pragma unroll
    for (int o = 16; o; o >>= 1) vs += __shfl_xor_sync(0xffffffffu, vs, o);
    const float rs = rsqrtf(vs * (1.0f / DIM) + LN_EPS);

    size_t base = (size_t)warp * DIM;
    #pragma unroll
    for (int j = 0; j < 16; j++) {
        int c = lane + 32 * j;
        float y = (x[j] - mu) * rs * g[c] + beta[c];
        __half h = __float2half_rn(y);
        g_Ah[base + c] = h;
        g_Al[base + c] = __float2half_rn(y - __half2float(h));
    }
}

// ---------------- kernel 4: heads + epilogue + rescue flagging ----------------
__global__ __launch_bounds__(256)
void head_kernel(const float* __restrict__ H,
                 const float* __restrict__ Wcls, const float* __restrict__ bcls,
                 const float* __restrict__ Wdist, const float* __restrict__ bdist,
                 const float* __restrict__ t1, const float* __restrict__ dist_in,
                 float* __restrict__ out)
{
    const int warp = (blockIdx.x * blockDim.x + threadIdx.x) >> 5;
    const int lane = threadIdx.x & 31;
    if (warp >= NRAYS) return;
    const float* row = H + (size_t)warp * DIM;

    float sc = 0.f, sd = 0.f;
    #pragma unroll
    for (int j = 0; j < 16; j++) {
        int c = lane + 32 * j;
        float h = fmaxf(row[c], 0.f);
        sc += h * Wcls[c];
        sd += h * Wdist[c];
    }
    #pragma unroll
    for (int o = 16; o; o >>= 1) {
        sc += __shfl_xor_sync(0xffffffffu, sc, o);
        sd += __shfl_xor_sync(0xffffffffu, sd, o);
    }

    if (lane == 0) {
        const int r = warp;
        float cls  = sc + bcls[0];
        float dist = (sd + bdist[0]) * g_len[r];
        bool  m    = (g_mask[r] != 0);
        float hit  = m ? cls : 0.f;
        float dval = (m ? dist : 0.f) + t1[r];
        float di   = dist_in[r];
        bool  up   = (hit > 0.f) && (dval < di) && m;
        out[r]         = hit;
        out[NRAYS + r] = up ? dval : di;
        if (m && fabsf(cls) < RESCUE_TAU) {
            int p = atomicAdd(&g_rescue_cnt, 1);
            if (p < RESCUE_CAP) g_rescue_list[p] = r;
        }
    }
}

// ---------------- kernel 5: exact fp32 rescue for borderline rays ----------------
__global__ __launch_bounds__(512)
void rescue_kernel(const float* __restrict__ orig, const float* __restrict__ vec,
                   const float* __restrict__ t1, const float* __restrict__ t2,
                   const float* __restrict__ nmin, const float* __restrict__ nmax,
                   const float* __restrict__ bbox, const int* __restrict__ idxs,
                   const float* __restrict__ b0, const float* __restrict__ bl,
                   const float* __restrict__ gl, const float* __restrict__ betal,
                   const float* __restrict__ Wcls, const float* __restrict__ bcls,
                   const float* __restrict__ Wdist, const float* __restrict__ bdist,
                   const float* __restrict__ dist_in, float* __restrict__ out)
{
    int cnt = g_rescue_cnt;
    if (cnt > RESCUE_CAP) cnt = RESCUE_CAP;
    int slot = blockIdx.x;
    if (slot >= cnt) return;
    const int r = g_rescue_list[slot];
    const int t = threadIdx.x;          // 512 threads; t == output dim j

    __shared__ float sX[KIN];           // 16 KB
    __shared__ float sF[1024];          // 4 KB
    __shared__ float sh[DIM];           // 2 KB
    __shared__ float sred[DIM];         // 2 KB

    const int nd = idxs[r];             // mask==1 for all rescued rays
    for (int i = t; i < 1024; i += 512) sF[i] = bbox[(size_t)nd * 1024 + i];

    // scalar setup (every thread computes the same values)
    float a = t1[r], b = t2[r];
    float ox, oy, oz, e0, e1, e2;
    {
        float o0 = orig[r*3], o1 = orig[r*3+1], o2 = orig[r*3+2];
        float v0 = vec[r*3],  v1 = vec[r*3+1],  v2 = vec[r*3+2];
        float s_ = b - a;
        float io0 = o0 + v0*a, io1 = o1 + v1*a, io2 = o2 + v2*a;
        float ie0 = io0 + v0*s_, ie1 = io1 + v1*s_, ie2 = io2 + v2*s_;
        float m0 = nmin[nd*3], m1 = nmin[nd*3+1], m2 = nmin[nd*3+2];
        float x0 = nmax[nd*3]   - m0;
        float x1 = nmax[nd*3+1] - m1;
        float x2 = nmax[nd*3+2] - m2;
        ox = fminf(fmaxf((io0 - m0)/x0, 0.f), 1.f);
        oy = fminf(fmaxf((io1 - m1)/x1, 0.f), 1.f);
        oz = fminf(fmaxf((io2 - m2)/x2, 0.f), 1.f);
        e0 = fminf(fmaxf((ie0 - m0)/x0, 0.f), 1.f);
        e1 = fminf(fmaxf((ie1 - m1)/x1, 0.f), 1.f);
        e2 = fminf(fmaxf((ie2 - m2)/x2, 0.f), 1.f);
    }
    __syncthreads();

    // recompute interp row in fp32
    for (int i = t; i < KIN; i += 512) {
        int p = i >> 7, f = i & 127;
        float tt = (float)p * (1.0f / (NPTS - 1));
        float x = ox + (e0 - ox)*tt, y = oy + (e1 - oy)*tt, z = oz + (e2 - oz)*tt;
        float ix = 1.f - x, iy = 1.f - y, iz = 1.f - z;
        sX[i] = (ix*iy*iz) * sF[0*128+f] + (x*iy*iz) * sF[1*128+f]
              + (ix*y*iz)  * sF[2*128+f] + (ix*iy*z) * sF[3*128+f]
              + (x*iy*z)   * sF[4*128+f] + (ix*y*z)  * sF[5*128+f]
              + (x*y*iz)   * sF[6*128+f] + (x*y*z)   * sF[7*128+f];
    }
    __syncthreads();

    // W0 matvec (coalesced via W0^T)
    float h;
    {
        float accv = b0[t];
        const float* wt = g_W0T;
        #pragma unroll 4
        for (int k = 0; k < KIN; k++) accv += sX[k] * wt[k * DIM + t];
        h = accv;
    }

    // 6 layers: relu -> LN -> matvec
    for (int i = 0; i < NLAYERS; i++) {
        float x = fmaxf(h, 0.f);
        sred[t] = x; __syncthreads();
        for (int s2 = 256; s2; s2 >>= 1) { if (t < s2) sred[t] += sred[t + s2]; __syncthreads(); }
        float mu = sred[0] * (1.0f / DIM); __syncthreads();
        float d = x - mu;
        sred[t] = d * d; __syncthreads();
        for (int s2 = 256; s2; s2 >>= 1) { if (t < s2) sred[t] += sred[t + s2]; __syncthreads(); }
        float rs = rsqrtf(sred[0] * (1.0f / DIM) + LN_EPS); __syncthreads();
        sh[t] = d * rs * gl[i * DIM + t] + betal[i * DIM + t];
        __syncthreads();
        float accv = bl[i * DIM + t];
        const float* wt = g_WlT + (size_t)i * DIM * DIM;
        #pragma unroll 4
        for (int k = 0; k < DIM; k++) accv += sh[k] * wt[k * DIM + t];
        h = accv;
        __syncthreads();
    }

    // heads
    float hh = fmaxf(h, 0.f);
    sred[t] = hh * Wcls[t]; __syncthreads();
    for (int s2 = 256; s2; s2 >>= 1) { if (t < s2) sred[t] += sred[t + s2]; __syncthreads(); }
    float cls = sred[0] + bcls[0]; __syncthreads();
    sred[t] = hh * Wdist[t]; __syncthreads();
    for (int s2 = 256; s2; s2 >>= 1) { if (t < s2) sred[t] += sred[t + s2]; __syncthreads(); }

    if (t == 0) {
        float dist = (sred[0] + bdist[0]) * g_len[r];
        float dval = dist + a;
        float di   = dist_in[r];
        bool  up   = (cls > 0.f) && (dval < di);
        out[r]         = cls;
        out[NRAYS + r] = up ? dval : di;
    }
}

// ---------------- launch ----------------
extern "C" void kernel_launch(void* const* d_in, const int* in_sizes, int n_in,
                              void* d_out, int out_size)
{
    const float* orig    = (const float*)d_in[0];
    const float* vec     = (const float*)d_in[1];
    const float* t1      = (const float*)d_in[2];
    const float* t2      = (const float*)d_in[3];
    const float* dist_in = (const float*)d_in[4];
    const float* nmin    = (const float*)d_in[5];
    const float* nmax    = (const float*)d_in[6];
    const float* bbox    = (const float*)d_in[7];
    const float* W0      = (const float*)d_in[8];
    const float* b0      = (const float*)d_in[9];
    const float* Wl      = (const float*)d_in[10];
    const float* bl      = (const float*)d_in[11];
    const float* gl      = (const float*)d_in[12];
    const float* betal   = (const float*)d_in[13];
    const float* Wcls    = (const float*)d_in[14];
    const float* bcls    = (const float*)d_in[15];
    const float* Wdist   = (const float*)d_in[16];
    const float* bdist   = (const float*)d_in[17];
    const int*   idxs    = (const int*)d_in[18];
    const void*  maskraw = (const void*)d_in[19];
    float* out = (float*)d_out;

    __half *pXh, *pXl, *pAh, *pAl, *pW0h, *pW0l, *pWlh, *pWll;
    float  *pHa, *pHb, *pW0T, *pWlT;
    cudaGetSymbolAddress((void**)&pXh,  g_Xh);
    cudaGetSymbolAddress((void**)&pXl,  g_Xl);
    cudaGetSymbolAddress((void**)&pAh,  g_Ah);
    cudaGetSymbolAddress((void**)&pAl,  g_Al);
    cudaGetSymbolAddress((void**)&pW0h, g_W0h);
    cudaGetSymbolAddress((void**)&pW0l, g_W0l);
    cudaGetSymbolAddress((void**)&pWlh, g_Wlh);
    cudaGetSymbolAddress((void**)&pWll, g_Wll);
    cudaGetSymbolAddress((void**)&pHa,  g_Ha);
    cudaGetSymbolAddress((void**)&pHb,  g_Hb);
    cudaGetSymbolAddress((void**)&pW0T, g_W0T);
    cudaGetSymbolAddress((void**)&pWlT, g_WlT);

    // 0) mask decode + counter zero
    mask_detect<<<1, 1024>>>((const unsigned*)maskraw);
    mask_decode<<<NRAYS / 256, 256>>>(maskraw);

    // 0b) weight prep: split to fp16 pairs + transpose for rescue
    split_kernel<<<(2097152 + 255) / 256, 256>>>(W0, pW0h, pW0l, 2097152);
    split_kernel<<<(1572864 + 255) / 256, 256>>>(Wl, pWlh, pWll, 1572864);
    transpose_k<<<dim3(KIN / 32, DIM / 32), dim3(32, 8)>>>(W0, pW0T, DIM, KIN);
    for (int i = 0; i < NLAYERS; i++)
        transpose_k<<<dim3(DIM / 32, DIM / 32), dim3(32, 8)>>>(
            Wl + (size_t)i * DIM * DIM, pWlT + (size_t)i * DIM * DIM, DIM, DIM);

    // 1) interp -> Xh/Xl
    interp_kernel<<<NRAYS, 128>>>(orig, vec, t1, t2, nmin, nmax, bbox, idxs);

    // 2) H = X @ W0^T + b0   (fp16x3 tensor-core GEMM)
    gemm_f16x3<<<dim3(NRAYS / 128, DIM / 128), 256>>>(pXh, pXl, pW0h, pW0l,
                                                      b0, pHa, NRAYS, DIM, KIN);

    // 3) 6 x (relu -> LN -> GEMM)
    float* cur = pHa;
    float* nxt = pHb;
    for (int i = 0; i < NLAYERS; i++) {
        relu_ln_kernel<<<(NRAYS * 32) / 256, 256>>>(cur, gl + i * DIM, betal + i * DIM);
        gemm_f16x3<<<dim3(NRAYS / 128, DIM / 128), 256>>>(
            pAh, pAl, pWlh + (size_t)i * DIM * DIM, pWll + (size_t)i * DIM * DIM,
            bl + i * DIM, nxt, NRAYS, DIM, DIM);
        float* tmp = cur; cur = nxt; nxt = tmp;
    }

    // 4) heads + select epilogue + rescue flagging
    head_kernel<<<(NRAYS * 32) / 256, 256>>>(cur, Wcls, bcls, Wdist, bdist,
                                             t1, dist_in, out);

    // 5) exact fp32 rescue for |cls| < tau rays
    rescue_kernel<<<RESCUE_CAP, 512>>>(orig, vec, t1, t2, nmin, nmax, bbox, idxs,
                                       b0, bl, gl, betal, Wcls, bcls, Wdist, bdist,
                                       dist_in, out);
}

// round 17
// speedup vs baseline: 2.2311x; 1.9261x over previous
#include <cuda_runtime.h>
#include <cuda_fp16.h>
#include <cstdint>
#include <cstddef>

#define NRAYS   65536
#define NPTS    32
#define FEAT    128
#define DIM     512
#define NLAYERS 6
#define KIN     4096
#define LN_EPS  1e-5f
#define RESCUE_CAP 16384
#define RESCUE_TAU 0.04f

// ---------------- scratch (device globals: allocation-free) ----------------
__device__ __half g_Xh[268435456];      // [NRAYS, KIN] fp16
__device__ float  g_Ha[33554432];       // [NRAYS, DIM] fp32
__device__ float  g_Hb[33554432];
__device__ __half g_Ah[33554432];       // post relu+LN fp16
__device__ __half g_W0h[2097152];       // W0 fp16
__device__ __half g_Wlh[1572864];       // Wl fp16 (6 layers)
__device__ float  g_W0T[2097152];       // W0^T for rescue
__device__ float  g_WlT[1572864];       // Wl^T per layer for rescue
__device__ float  g_len[NRAYS];
__device__ int    g_mask_mode;
__device__ unsigned char g_mask[NRAYS];
__device__ int    g_rescue_cnt;
__device__ int    g_rescue_list[RESCUE_CAP];

// ---------------- mask sniff + decode (proven) ----------------
__global__ void mask_detect(const unsigned* __restrict__ w)
{
    __shared__ int s_u8, s_bf16;
    if (threadIdx.x == 0) { s_u8 = 0; s_bf16 = 0; }
    __syncthreads();
    int u8 = 0, bf = 0;
    for (int i = threadIdx.x; i < 16384; i += blockDim.x) {
        unsigned v = w[i];
        if (v == 0x3F803F80u || v == 0x00003F80u) bf = 1;
        else if (v > 1u && (v & ~0x01010101u) == 0u) u8 = 1;
    }
    if (u8) atomicOr(&s_u8, 1);
    if (bf) atomicOr(&s_bf16, 1);
    __syncthreads();
    if (threadIdx.x == 0) {
        int mode = 0;
        if (s_bf16) mode = 3;
        if (s_u8)   mode = 2;
        g_mask_mode = mode;
        g_rescue_cnt = 0;
    }
}

__global__ void mask_decode(const void* __restrict__ mp)
{
    int r = blockIdx.x * blockDim.x + threadIdx.x;
    if (r >= NRAYS) return;
    int mode = g_mask_mode;
    unsigned char m;
    if (mode == 2)      m = (((const unsigned char*)mp)[r]  != 0);
    else if (mode == 3) m = (((const unsigned short*)mp)[r] != 0);
    else                m = (((const unsigned*)mp)[r]       != 0);
    g_mask[r] = m;
}

// ---------------- weight prep ----------------
__global__ void to_half_kernel(const float* __restrict__ s, __half* __restrict__ d, int n)
{
    int i = blockIdx.x * blockDim.x + threadIdx.x;
    if (i < n) d[i] = __float2half_rn(s[i]);
}

__global__ void transpose_k(const float* __restrict__ src, float* __restrict__ dst,
                            int R, int C)
{
    __shared__ float tile[32][33];
    int bx = blockIdx.x * 32, by = blockIdx.y * 32;
    int tx = threadIdx.x, ty = threadIdx.y;
    #pragma unroll
    for (int i = 0; i < 32; i += 8) {
        int rr = by + ty + i, cc = bx + tx;
        if (rr < R && cc < C) tile[ty + i][tx] = src[(size_t)rr * C + cc];
    }
    __syncthreads();
    #pragma unroll
    for (int i = 0; i < 32; i += 8) {
        int cc = bx + ty + i, rr = by + tx;
        if (cc < C && rr < R) dst[(size_t)cc * R + rr] = tile[tx][ty + i];
    }
}

// ---------------- kernel 1: trilinear interp -> Xh ----------------
__global__ __launch_bounds__(128)
void interp_kernel(const float* __restrict__ orig, const float* __restrict__ vec,
                   const float* __restrict__ t1, const float* __restrict__ t2,
                   const float* __restrict__ nmin, const float* __restrict__ nmax,
                   const float* __restrict__ bbox, const int* __restrict__ idxs)
{
    const int r = blockIdx.x;
    const int tid = threadIdx.x;
    __shared__ float sf[8][FEAT];
    __shared__ float so[3], se[3];

    const int idx = (g_mask[r] != 0) ? idxs[r] : 0;

    const float4* fsrc = (const float4*)(bbox + (size_t)idx * 1024);
    float4* fdst = (float4*)&sf[0][0];
    fdst[tid]       = fsrc[tid];
    fdst[tid + 128] = fsrc[tid + 128];

    if (tid < 3) {
        float o_  = orig[r * 3 + tid];
        float v   = vec [r * 3 + tid];
        float a   = t1[r], b = t2[r];
        float io  = o_ + v * a;
        float iv  = v * (b - a);
        float ie  = io + iv;
        float mn  = nmin[idx * 3 + tid];
        float ext = nmax[idx * 3 + tid] - mn;
        so[tid] = fminf(fmaxf((io - mn) / ext, 0.f), 1.f);
        se[tid] = fminf(fmaxf((ie - mn) / ext, 0.f), 1.f);
    }
    if (tid == 0) {
        float s = t2[r] - t1[r];
        float vx = vec[r*3+0] * s, vy = vec[r*3+1] * s, vz = vec[r*3+2] * s;
        g_len[r] = sqrtf(vx*vx + vy*vy + vz*vz);
    }
    __syncthreads();

    const float ox = so[0], oy = so[1], oz = so[2];
    const float dx = se[0] - ox, dy = se[1] - oy, dz = se[2] - oz;

    const float f0 = sf[0][tid], f1 = sf[1][tid], f2 = sf[2][tid], f3 = sf[3][tid];
    const float f4 = sf[4][tid], f5 = sf[5][tid], f6 = sf[6][tid], f7 = sf[7][tid];

    size_t base = (size_t)r * KIN;
    #pragma unroll
    for (int p = 0; p < NPTS; p++) {
        float t = (float)p * (1.0f / (NPTS - 1));
        float x = ox + dx * t, y = oy + dy * t, z = oz + dz * t;
        float ix = 1.f - x, iy = 1.f - y, iz = 1.f - z;
        float v = (ix*iy*iz) * f0 + (x*iy*iz) * f1 + (ix*y*iz) * f2 + (ix*iy*z) * f3
                + (x*iy*z)  * f4 + (ix*y*z)  * f5 + (x*y*iz)  * f6 + (x*y*z)   * f7;
        g_Xh[base + p * FEAT + tid] = __float2half_rn(v);
    }
}

// ================= fp16 TN GEMM on tensor cores (mma.sync) =================
// C[M,N] = A[M,K] @ W[N,K]^T + bias.  BM=128, BN=256, BK=64, 256 thr (8 warps
// as 2m x 4n, warp tile 64x64).  3-stage cp.async pipeline.
// smem rows padded to 72 halves (bank-conflict-free frag loads).
#define SROW    72                       // halves per smem row
#define STG_HV  27648u                   // halves per stage (A 9216 + W 18432)
#define STG_BY  55296u                   // bytes per stage
#define OFF_WBY 18432u                   // W byte offset within stage

static __device__ __forceinline__ void cp16(uint32_t s, const void* g)
{
    asm volatile("cp.async.cg.shared.global [%0], [%1], 16;" :: "r"(s), "l"(g));
}
#define MMA16816(d, a, b) \
    asm volatile("mma.sync.aligned.m16n8k16.row.col.f32.f16.f16.f32 " \
        "{%0,%1,%2,%3},{%4,%5,%6,%7},{%8,%9},{%0,%1,%2,%3};" \
        : "+f"(d[0]), "+f"(d[1]), "+f"(d[2]), "+f"(d[3]) \
        : "r"(a[0]), "r"(a[1]), "r"(a[2]), "r"(a[3]), "r"(b[0]), "r"(b[1]))

static __device__ __forceinline__ void load_stage_h(
    uint32_t su, const __half* __restrict__ A, const __half* __restrict__ W,
    int bm, int bn, int K, int k0, int tid)
{
    #pragma unroll
    for (int it = 0; it < 4; it++) {                 // A: 128 rows x 8 chunks
        int i = tid + it * 256;
        int r = i >> 3, c = i & 7;
        cp16(su + (uint32_t)(r * 144 + c * 16), A + (size_t)(bm + r) * K + k0 + c * 8);
    }
    #pragma unroll
    for (int it = 0; it < 8; it++) {                 // W: 256 rows x 8 chunks
        int i = tid + it * 256;
        int r = i >> 3, c = i & 7;
        cp16(su + OFF_WBY + (uint32_t)(r * 144 + c * 16),
             W + (size_t)(bn + r) * K + k0 + c * 8);
    }
}

__global__ __launch_bounds__(256, 1)
void gemm_h(const __half* __restrict__ A, const __half* __restrict__ W,
            const float* __restrict__ bias, float* __restrict__ C,
            int K, int Nout)
{
    extern __shared__ __align__(16) __half sm[];
    const uint32_t smu = (uint32_t)__cvta_generic_to_shared(sm);

    const int tid  = threadIdx.x;
    const int lane = tid & 31;
    const int wid  = tid >> 5;
    const int wm   = wid >> 2;            // 0..1
    const int wn   = wid & 3;             // 0..3
    const int g    = lane >> 2;           // 0..7
    const int c4   = lane & 3;            // 0..3
    const int bm   = blockIdx.x * 128;
    const int bn   = blockIdx.y * 256;

    float acc[4][8][4];
    #pragma unroll
    for (int i = 0; i < 4; i++)
        #pragma unroll
        for (int j = 0; j < 8; j++)
            #pragma unroll
            for (int q = 0; q < 4; q++) acc[i][j][q] = 0.f;

    const int NS = K >> 6;                // K/64 chunks

    #pragma unroll
    for (int s = 0; s < 3; s++) {         // prologue (NS >= 3 always here)
        load_stage_h(smu + s * STG_BY, A, W, bm, bn, K, s * 64, tid);
        asm volatile("cp.async.commit_group;");
    }

    for (int s = 0; s < NS; s++) {
        asm volatile("cp.async.wait_group 2;");
        __syncthreads();
        const __half* sa = sm + (uint32_t)(s % 3) * STG_HV;
        const __half* sw = sa + 9216;

        #pragma unroll
        for (int kk = 0; kk < 4; kk++) {
            uint32_t Af[4][4];
            #pragma unroll
            for (int mt = 0; mt < 4; mt++) {
                int r0 = wm * 64 + mt * 16 + g;
                const __half* p0 = sa + r0 * SROW + kk * 16 + 2 * c4;
                Af[mt][0] = *(const uint32_t*)(p0);
                Af[mt][1] = *(const uint32_t*)(p0 + 8 * SROW);
                Af[mt][2] = *(const uint32_t*)(p0 + 8);
                Af[mt][3] = *(const uint32_t*)(p0 + 8 * SROW + 8);
            }
            uint32_t Bf[8][2];
            #pragma unroll
            for (int nt = 0; nt < 8; nt++) {
                int rn = wn * 64 + nt * 8 + g;
                const __half* p0 = sw + rn * SROW + kk * 16 + 2 * c4;
                Bf[nt][0] = *(const uint32_t*)(p0);
                Bf[nt][1] = *(const uint32_t*)(p0 + 8);
            }
            #pragma unroll
            for (int mt = 0; mt < 4; mt++)
                #pragma unroll
                for (int nt = 0; nt < 8; nt++)
                    MMA16816(acc[mt][nt], Af[mt], Bf[nt]);
        }
        __syncthreads();

        if (s + 3 < NS)
            load_stage_h(smu + (uint32_t)((s + 3) % 3) * STG_BY, A, W, bm, bn, K,
                         (s + 3) * 64, tid);
        asm volatile("cp.async.commit_group;");
    }

    // epilogue
    float2 bb[8];
    #pragma unroll
    for (int nt = 0; nt < 8; nt++)
        bb[nt] = *(const float2*)&bias[bn + wn * 64 + nt * 8 + c4 * 2];

    #pragma unroll
    for (int mt = 0; mt < 4; mt++) {
        int m = bm + wm * 64 + mt * 16 + g;
        #pragma unroll
        for (int nt = 0; nt < 8; nt++) {
            int n = bn + wn * 64 + nt * 8 + c4 * 2;
            float2 v0 = make_float2(acc[mt][nt][0] + bb[nt].x, acc[mt][nt][1] + bb[nt].y);
            float2 v1 = make_float2(acc[mt][nt][2] + bb[nt].x, acc[mt][nt][3] + bb[nt].y);
            *(float2*)&C[(size_t)m * Nout + n]       = v0;
            *(float2*)&C[(size_t)(m + 8) * Nout + n] = v1;
        }
    }
}

// ---------------- relu + layernorm -> fp16 ----------------
__global__ __launch_bounds__(256)
void relu_ln_kernel(const float* __restrict__ H, const float* __restrict__ g,
                    const float* __restrict__ beta)
{
    const int warp = (blockIdx.x * blockDim.x + threadIdx.x) >> 5;
    const int lane = threadIdx.x & 31;
    if (warp >= NRAYS) return;
    const float* row = H + (size_t)warp * DIM;

    float x[16];
    float s = 0.f;
    #pragma unroll
    for (int j = 0; j < 16; j++) {
        x[j] = fmaxf(row[lane + 32 * j], 0.f);
        s += x[j];
    }
    #pragma unroll
    for (int o = 16; o; o >>= 1) s += __shfl_xor_sync(0xffffffffu, s, o);
    const float mu = s * (1.0f / DIM);

    float vs = 0.f;
    #pragma unroll
    for (int j = 0; j < 16; j++) { float d = x[j] - mu; vs += d * d; }
    #pragma unroll
    for (int o = 16; o; o >>= 1) vs += __shfl_xor_sync(0xffffffffu, vs, o);
    const float rs = rsqrtf(vs * (1.0f / DIM) + LN_EPS);

    size_t base = (size_t)warp * DIM;
    #pragma unroll
    for (int j = 0; j < 16; j++) {
        int c = lane + 32 * j;
        g_Ah[base + c] = __float2half_rn((x[j] - mu) * rs * g[c] + beta[c]);
    }
}

// ---------------- heads + epilogue + rescue flagging ----------------
__global__ __launch_bounds__(256)
void head_kernel(const float* __restrict__ H,
                 const float* __restrict__ Wcls, const float* __restrict__ bcls,
                 const float* __restrict__ Wdist, const float* __restrict__ bdist,
                 const float* __restrict__ t1, const float* __restrict__ dist_in,
                 float* __restrict__ out)
{
    const int warp = (blockIdx.x * blockDim.x + threadIdx.x) >> 5;
    const int lane = threadIdx.x & 31;
    if (warp >= NRAYS) return;
    const float* row = H + (size_t)warp * DIM;

    float sc = 0.f, sd = 0.f;
    #pragma unroll
    for (int j = 0; j < 16; j++) {
        int c = lane + 32 * j;
        float h = fmaxf(row[c], 0.f);
        sc += h * Wcls[c];
        sd += h * Wdist[c];
    }
    #pragma unroll
    for (int o = 16; o; o >>= 1) {
        sc += __shfl_xor_sync(0xffffffffu, sc, o);
        sd += __shfl_xor_sync(0xffffffffu, sd, o);
    }

    if (lane == 0) {
        const int r = warp;
        float cls  = sc + bcls[0];
        float dist = (sd + bdist[0]) * g_len[r];
        bool  m    = (g_mask[r] != 0);
        float hit  = m ? cls : 0.f;
        float dval = (m ? dist : 0.f) + t1[r];
        float di   = dist_in[r];
        bool  up   = (hit > 0.f) && (dval < di) && m;
        out[r]         = hit;
        out[NRAYS + r] = up ? dval : di;
        if (m && fabsf(cls) < RESCUE_TAU) {
            int p = atomicAdd(&g_rescue_cnt, 1);
            if (p < RESCUE_CAP) g_rescue_list[p] = r;
        }
    }
}

// ---------------- exact fp32 rescue ----------------
__global__ __launch_bounds__(512)
void rescue_kernel(const float* __restrict__ orig, const float* __restrict__ vec,
                   const float* __restrict__ t1, const float* __restrict__ t2,
                   const float* __restrict__ nmin, const float* __restrict__ nmax,
                   const float* __restrict__ bbox, const int* __restrict__ idxs,
                   const float* __restrict__ b0, const float* __restrict__ bl,
                   const float* __restrict__ gl, const float* __restrict__ betal,
                   const float* __restrict__ Wcls, const float* __restrict__ bcls,
                   const float* __restrict__ Wdist, const float* __restrict__ bdist,
                   const float* __restrict__ dist_in, float* __restrict__ out)
{
    int cnt = g_rescue_cnt;
    if (cnt > RESCUE_CAP) cnt = RESCUE_CAP;
    int slot = blockIdx.x;
    if (slot >= cnt) return;
    const int r = g_rescue_list[slot];
    const int t = threadIdx.x;

    __shared__ float sX[KIN];
    __shared__ float sF[1024];
    __shared__ float sh[DIM];
    __shared__ float sred[DIM];

    const int nd = idxs[r];
    for (int i = t; i < 1024; i += 512) sF[i] = bbox[(size_t)nd * 1024 + i];

    float a = t1[r], b = t2[r];
    float ox, oy, oz, e0, e1, e2;
    {
        float o0 = orig[r*3], o1 = orig[r*3+1], o2 = orig[r*3+2];
        float v0 = vec[r*3],  v1 = vec[r*3+1],  v2 = vec[r*3+2];
        float s_ = b - a;
        float io0 = o0 + v0*a, io1 = o1 + v1*a, io2 = o2 + v2*a;
        float ie0 = io0 + v0*s_, ie1 = io1 + v1*s_, ie2 = io2 + v2*s_;
        float m0 = nmin[nd*3], m1 = nmin[nd*3+1], m2 = nmin[nd*3+2];
        float x0 = nmax[nd*3]   - m0;
        float x1 = nmax[nd*3+1] - m1;
        float x2 = nmax[nd*3+2] - m2;
        ox = fminf(fmaxf((io0 - m0)/x0, 0.f), 1.f);
        oy = fminf(fmaxf((io1 - m1)/x1, 0.f), 1.f);
        oz = fminf(fmaxf((io2 - m2)/x2, 0.f), 1.f);
        e0 = fminf(fmaxf((ie0 - m0)/x0, 0.f), 1.f);
        e1 = fminf(fmaxf((ie1 - m1)/x1, 0.f), 1.f);
        e2 = fminf(fmaxf((ie2 - m2)/x2, 0.f), 1.f);
    }
    __syncthreads();

    for (int i = t; i < KIN; i += 512) {
        int p = i >> 7, f = i & 127;
        float tt = (float)p * (1.0f / (NPTS - 1));
        float x = ox + (e0 - ox)*tt, y = oy + (e1 - oy)*tt, z = oz + (e2 - oz)*tt;
        float ix = 1.f - x, iy = 1.f - y, iz = 1.f - z;
        sX[i] = (ix*iy*iz) * sF[0*128+f] + (x*iy*iz) * sF[1*128+f]
              + (ix*y*iz)  * sF[2*128+f] + (ix*iy*z) * sF[3*128+f]
              + (x*iy*z)   * sF[4*128+f] + (ix*y*z)  * sF[5*128+f]
              + (x*y*iz)   * sF[6*128+f] + (x*y*z)   * sF[7*128+f];
    }
    __syncthreads();

    float h;
    {
        float accv = b0[t];
        const float* wt = g_W0T;
        #pragma unroll 4
        for (int k = 0; k < KIN; k++) accv += sX[k] * wt[k * DIM + t];
        h = accv;
    }

    for (int i = 0; i < NLAYERS; i++) {
        float x = fmaxf(h, 0.f);
        sred[t] = x; __syncthreads();
        for (int s2 = 256; s2; s2 >>= 1) { if (t < s2) sred[t] += sred[t + s2]; __syncthreads(); }
        float mu = sred[0] * (1.0f / DIM); __syncthreads();
        float d = x - mu;
        sred[t] = d * d; __syncthreads();
        for (int s2 = 256; s2; s2 >>= 1) { if (t < s2) sred[t] += sred[t + s2]; __syncthreads(); }
        float rs = rsqrtf(sred[0] * (1.0f / DIM) + LN_EPS); __syncthreads();
        sh[t] = d * rs * gl[i * DIM + t] + betal[i * DIM + t];
        __syncthreads();
        float accv = bl[i * DIM + t];
        const float* wt = g_WlT + (size_t)i * DIM * DIM;
        #pragma unroll 4
        for (int k = 0; k < DIM; k++) accv += sh[k] * wt[k * DIM + t];
        h = accv;
        __syncthreads();
    }

    float hh = fmaxf(h, 0.f);
    sred[t] = hh * Wcls[t]; __syncthreads();
    for (int s2 = 256; s2; s2 >>= 1) { if (t < s2) sred[t] += sred[t + s2]; __syncthreads(); }
    float cls = sred[0] + bcls[0]; __syncthreads();
    sred[t] = hh * Wdist[t]; __syncthreads();
    for (int s2 = 256; s2; s2 >>= 1) { if (t < s2) sred[t] += sred[t + s2]; __syncthreads(); }

    if (t == 0) {
        float dist = (sred[0] + bdist[0]) * g_len[r];
        float dval = dist + a;
        float di   = dist_in[r];
        bool  up   = (cls > 0.f) && (dval < di);
        out[r]         = cls;
        out[NRAYS + r] = up ? dval : di;
    }
}

// ---------------- launch ----------------
extern "C" void kernel_launch(void* const* d_in, const int* in_sizes, int n_in,
                              void* d_out, int out_size)
{
    const float* orig    = (const float*)d_in[0];
    const float* vec     = (const float*)d_in[1];
    const float* t1      = (const float*)d_in[2];
    const float* t2      = (const float*)d_in[3];
    const float* dist_in = (const float*)d_in[4];
    const float* nmin    = (const float*)d_in[5];
    const float* nmax    = (const float*)d_in[6];
    const float* bbox    = (const float*)d_in[7];
    const float* W0      = (const float*)d_in[8];
    const float* b0      = (const float*)d_in[9];
    const float* Wl      = (const float*)d_in[10];
    const float* bl      = (const float*)d_in[11];
    const float* gl      = (const float*)d_in[12];
    const float* betal   = (const float*)d_in[13];
    const float* Wcls    = (const float*)d_in[14];
    const float* bcls    = (const float*)d_in[15];
    const float* Wdist   = (const float*)d_in[16];
    const float* bdist   = (const float*)d_in[17];
    const int*   idxs    = (const int*)d_in[18];
    const void*  maskraw = (const void*)d_in[19];
    float* out = (float*)d_out;

    __half *pXh, *pAh, *pW0h, *pWlh;
    float  *pHa, *pHb, *pW0T, *pWlT;
    cudaGetSymbolAddress((void**)&pXh,  g_Xh);
    cudaGetSymbolAddress((void**)&pAh,  g_Ah);
    cudaGetSymbolAddress((void**)&pW0h, g_W0h);
    cudaGetSymbolAddress((void**)&pWlh, g_Wlh);
    cudaGetSymbolAddress((void**)&pHa,  g_Ha);
    cudaGetSymbolAddress((void**)&pHb,  g_Hb);
    cudaGetSymbolAddress((void**)&pW0T, g_W0T);
    cudaGetSymbolAddress((void**)&pWlT, g_WlT);

    const int SMEM_SZ = 3 * (int)STG_BY;            // 165,888 B dynamic
    static int smem_set = 0;
    if (!smem_set) {
        cudaFuncSetAttribute(gemm_h, cudaFuncAttributeMaxDynamicSharedMemorySize, SMEM_SZ);
        smem_set = 1;
    }

    // 0) mask decode + rescue counter zero
    mask_detect<<<1, 1024>>>((const unsigned*)maskraw);
    mask_decode<<<NRAYS / 256, 256>>>(maskraw);

    // 0b) weight prep: fp16 convert + transposes for exact rescue
    to_half_kernel<<<(2097152 + 255) / 256, 256>>>(W0, pW0h, 2097152);
    to_half_kernel<<<(1572864 + 255) / 256, 256>>>(Wl, pWlh, 1572864);
    transpose_k<<<dim3(KIN / 32, DIM / 32), dim3(32, 8)>>>(W0, pW0T, DIM, KIN);
    for (int i = 0; i < NLAYERS; i++)
        transpose_k<<<dim3(DIM / 32, DIM / 32), dim3(32, 8)>>>(
            Wl + (size_t)i * DIM * DIM, pWlT + (size_t)i * DIM * DIM, DIM, DIM);

    // 1) interp -> Xh
    interp_kernel<<<NRAYS, 128>>>(orig, vec, t1, t2, nmin, nmax, bbox, idxs);

    // 2) H = X @ W0^T + b0
    gemm_h<<<dim3(NRAYS / 128, DIM / 256), 256, SMEM_SZ>>>(pXh, pW0h, b0, pHa, KIN, DIM);

    // 3) 6 x (relu -> LN -> GEMM)
    float* cur = pHa;
    float* nxt = pHb;
    for (int i = 0; i < NLAYERS; i++) {
        relu_ln_kernel<<<(NRAYS * 32) / 256, 256>>>(cur, gl + i * DIM, betal + i * DIM);
        gemm_h<<<dim3(NRAYS / 128, DIM / 256), 256, SMEM_SZ>>>(
            pAh, pWlh + (size_t)i * DIM * DIM, bl + i * DIM, nxt, DIM, DIM);
        float* tmp = cur; cur = nxt; nxt = tmp;
    }

    // 4) heads + epilogue + rescue flagging
    head_kernel<<<(NRAYS * 32) / 256, 256>>>(cur, Wcls, bcls, Wdist, bdist,
                                             t1, dist_in, out);

    // 5) exact fp32 rescue for |cls| < tau rays
    rescue_kernel<<<RESCUE_CAP, 512>>>(orig, vec, t1, t2, nmin, nmax, bbox, idxs,
                                       b0, bl, gl, betal, Wcls, bcls, Wdist, bdist,
                                       dist_in, out);
}